// round 14
// baseline (speedup 1.0000x reference)
#include <cuda_runtime.h>
#include <cuda_fp16.h>
#include <cstdint>
#include <math.h>

#define DINLINE __device__ __forceinline__

constexpr int B_ = 256;
constexpr int C_ = 256;
constexpr int HW_ = 225;
constexpr int S_ = 8;
constexpr int NELEM = B_ * C_ * HW_;      // 14,745,600
constexpr int NPIX = B_ * HW_;            // 57600
constexpr int UPD_BLOCKS = 15;
constexpr int PADP = 21;
constexpr int TAPS_TOTAL = 92;
constexpr int MTILES = 450;               // 57600 / 128

// ---------------- scratch ---------------------------------------------------
__device__ __half g_xph[(size_t)B_ * PADP * PADP * C_];
__device__ __half g_wh[(size_t)TAPS_TOTAL * C_ * C_];
__device__ __half g_wfh[4 * C_ * C_];
__device__ __half g_wfl[4 * C_ * C_];
__device__ __half g_w1h[C_ * C_];
__device__ __half g_w1l[C_ * C_];
__device__ __half g_cath[(size_t)NPIX * 1024];     // channels-last concat (fp16)
__device__ float g_xc[NELEM];                       // channels-last [b][p][c]
__device__ __half g_xch[NELEM];
__device__ __half g_ybufh[NELEM];                   // y (pre-LN), fp16
__device__ __half g_nzh[(size_t)S_ * NELEM];        // noise, fp16
__device__ float g_lnwt[C_ * HW_];                  // [p][c]
__device__ float g_lnbt[C_ * HW_];
__device__ float g_stats3[2 * MTILES * 4];          // y-stat partials per CTA
__device__ float g_stats2[(size_t)S_ * B_ * UPD_BLOCKS * 2];

// conv parameter tables
__constant__ int c_taps[4]   = {9, 9, 25, 49};
__constant__ int c_kw[4]     = {3, 3, 5, 7};
__constant__ int c_dil[4]    = {1, 2, 1, 1};
__constant__ int c_pad[4]    = {1, 2, 2, 3};
__constant__ int c_tapoff[4] = {0, 9, 18, 43};
__constant__ int c_cooff[4]  = {0, 256, 512, 768};

// ---------------- helpers ---------------------------------------------------
DINLINE float elu_f(float v) { return v > 0.f ? v : expm1f(v); }
DINLINE uint32_t rotl32(uint32_t v, int s) { return __funnelshift_l(v, v, s); }

DINLINE void threefry2x32(uint32_t k0, uint32_t k1, uint32_t& x0, uint32_t& x1) {
    uint32_t k2 = k0 ^ k1 ^ 0x1BD11BDAu;
    x0 += k0; x1 += k1;
#define TF_R(r) { x0 += x1; x1 = rotl32(x1, r); x1 ^= x0; }
    TF_R(13) TF_R(15) TF_R(26) TF_R(6)
    x0 += k1; x1 += k2 + 1u;
    TF_R(17) TF_R(29) TF_R(16) TF_R(24)
    x0 += k2; x1 += k0 + 2u;
    TF_R(13) TF_R(15) TF_R(26) TF_R(6)
    x0 += k0; x1 += k1 + 3u;
    TF_R(17) TF_R(29) TF_R(16) TF_R(24)
    x0 += k1; x1 += k2 + 4u;
    TF_R(13) TF_R(15) TF_R(26) TF_R(6)
    x0 += k2; x1 += k0 + 5u;
#undef TF_R
}

DINLINE uint32_t smem_to_u32(const void* p) {
    uint32_t a;
    asm("{ .reg .u64 t; cvta.to.shared.u64 t, %1; cvt.u32.u64 %0, t; }"
        : "=r"(a) : "l"(p));
    return a;
}
DINLINE void ldm_x4(uint32_t* r, uint32_t addr) {
    asm volatile("ldmatrix.sync.aligned.m8n8.x4.shared.b16 {%0,%1,%2,%3}, [%4];"
                 : "=r"(r[0]), "=r"(r[1]), "=r"(r[2]), "=r"(r[3]) : "r"(addr));
}
DINLINE void mma_f16(float* c, const uint32_t* a, const uint32_t* b) {
    asm volatile(
        "mma.sync.aligned.m16n8k16.row.col.f32.f16.f16.f32 "
        "{%0,%1,%2,%3}, {%4,%5,%6,%7}, {%8,%9}, {%0,%1,%2,%3};"
        : "+f"(c[0]), "+f"(c[1]), "+f"(c[2]), "+f"(c[3])
        : "r"(a[0]), "r"(a[1]), "r"(a[2]), "r"(a[3]), "r"(b[0]), "r"(b[1]));
}
DINLINE void cp16(uint32_t dst, const void* src) {
    asm volatile("cp.async.cg.shared.global [%0], [%1], 16;" :: "r"(dst), "l"(src));
}
DINLINE void cp_commit() { asm volatile("cp.async.commit_group;"); }
template <int N> DINLINE void cp_wait() { asm volatile("cp.async.wait_group %0;" :: "n"(N)); }

DINLINE void split_fp16(float v, __half& h, __half& l) {
    h = __float2half_rn(v);
    l = __float2half_rn(v - __half2float(h));
}

// ---------------- prep kernels ----------------------------------------------
__global__ void pad_h_kernel(const float* __restrict__ x) {
    int c = threadIdx.x;
    int b = blockIdx.x;
    int pp = blockIdx.y;
    int py = pp / PADP, px = pp - py * PADP;
    float v = 0.f;
    int iy = py - 3, ix = px - 3;
    if (iy >= 0 && iy < 15 && ix >= 0 && ix < 15)
        v = x[((size_t)b * C_ + c) * HW_ + iy * 15 + ix];
    g_xph[((size_t)b * (PADP * PADP) + pp) * C_ + c] = __float2half_rn(v);
}

__global__ void wconv_kernel(const float* __restrict__ w, int taps, int tap_off) {
    int idx = blockIdx.x * 256 + threadIdx.x;
    if (idx >= C_ * C_ * taps) return;
    int tap = idx % taps;
    int rest = idx / taps;
    int ci = rest & 255;
    int co = rest >> 8;
    g_wh[((size_t)(tap_off + tap) * C_ + co) * C_ + ci] = __float2half_rn(w[idx]);
}

__global__ void wsplit1_kernel(const float* __restrict__ w,
                               __half* __restrict__ h, __half* __restrict__ l, int n) {
    int idx = blockIdx.x * 256 + threadIdx.x;
    if (idx >= n) return;
    split_fp16(w[idx], h[idx], l[idx]);
}

__global__ void lnT_kernel(const float* __restrict__ lnw, const float* __restrict__ lnb) {
    int p = blockIdx.x, c = threadIdx.x;
    g_lnwt[p * 256 + c] = lnw[c * 225 + p];
    g_lnbt[p * 256 + c] = lnb[c * 225 + p];
}

// ---------------- noise pre-generation (stream 2, fp16 out) ------------------
__global__ void __launch_bounds__(256)
noise_kernel(int step) {
    int b = blockIdx.x, yb = blockIdx.y, t = threadIdx.x;
    uint32_t fk0 = 0u, fk1 = (uint32_t)step;
    threefry2x32(0u, 42u, fk0, fk1);
    __half* o = g_nzh + (size_t)step * NELEM + (size_t)b * 57600;
#pragma unroll
    for (int e = 0; e < 15; e++) {
        int p = yb * 15 + e;
        uint32_t c0 = 0u, c1 = (uint32_t)((b * 256 + t) * 225 + p);
        threefry2x32(fk0, fk1, c0, c1);
        uint32_t bits = c0 ^ c1;
        float u = __uint_as_float(0x3f800000u | (bits >> 9)) - 1.0f;
        o[p * 256 + t] = __float2half_rn(u);
    }
}

// ---------------- unified HMMA kernel ---------------------------------------
// CTA 128 px x 128 ch; 8 warps 2x4, warp 64x32. STAGES-deep cp.async pipeline.
// TERMS=1: acc = A*Bh.  TERMS=2: acc = A*Bh + A*Bl (B split fp16).
constexpr int EPI_CONV = 0, EPI_FUSION = 1, EPI_STEP = 2;
constexpr int RSTR = 40;                    // fp16 per row (80B)
constexpr int ARRB = 128 * RSTR * 2;        // 10240 B
constexpr int hsmem(int terms, int stages) { return stages * (1 + terms) * ARRB; }

template <int KDIM, int EPI, bool GATHER, int TERMS, int STAGES>
__global__ void __launch_bounds__(256, 2)
hmma_kernel(const __half* __restrict__ A,
            const __half* __restrict__ BH, const __half* __restrict__ BL,
            const float* __restrict__ bs0, const float* __restrict__ bs1,
            const float* __restrict__ bs2, const float* __restrict__ bs3,
            __half* __restrict__ oh, float* __restrict__ of)
{
    constexpr int NARR = 1 + TERMS;
    constexpr int CHUNKB = NARR * ARRB;
    extern __shared__ __align__(16) char sm[];
    uint32_t smb = smem_to_u32(sm);

    int z = GATHER ? blockIdx.z : 0;
    int taps = GATHER ? c_taps[z] : 1;
    int kw = GATHER ? c_kw[z] : 1;
    int dil = GATHER ? c_dil[z] : 1;
    int off0 = GATHER ? (3 - c_pad[z]) : 0;
    int tap_off = GATHER ? c_tapoff[z] : 0;
    int co_off = GATHER ? c_cooff[z] : 0;
    int NCH = GATHER ? taps * 8 : KDIM / 32;
    const float* bias = (z == 0) ? bs0 : (z == 1) ? bs1 : (z == 2) ? bs2 : bs3;

    int t = threadIdx.x, lane = t & 31, wid = t >> 5;
    int wm = wid >> 2, wn = wid & 3;
    int row = t >> 1, q0 = (t & 1) * 2;
    int gp = blockIdx.x * 128 + row;
    int b = gp / 225, rem = gp - b * 225, y = rem / 15, xx = rem - y * 15;
    int coBase = blockIdx.y * 128;
    int bco = coBase + row;
    int sy0 = y + off0, sx0 = xx + off0;

    int ag = lane >> 3, alr = lane & 7;
    int a_row = (ag & 1) * 8 + alr, a_kb = (ag >> 1) * 16;
    int b_row = (ag >> 1) * 8 + alr, b_kb = (ag & 1) * 16;

    float acc[4][4][4];
#pragma unroll
    for (int i = 0; i < 4; i++)
#pragma unroll
        for (int j = 0; j < 4; j++)
#pragma unroll
            for (int k = 0; k < 4; k++) acc[i][j][k] = 0.f;

    auto stage = [&](int ch) {
        int tap = GATHER ? (ch >> 3) : 0;
        int ci0 = (GATHER ? (ch & 7) : ch) * 32;
        uint32_t base = smb + (uint32_t)(ch % STAGES) * CHUNKB;
        size_t asrc;
        if (GATHER) {
            int ky = tap / kw, kx = tap - ky * kw;
            asrc = (((size_t)b * PADP + (sy0 + ky * dil)) * PADP + (sx0 + kx * dil)) * C_ + ci0;
        } else {
            asrc = (size_t)gp * KDIM + ci0;
        }
        size_t bsrc = GATHER ? (((size_t)(tap_off + tap) * C_ + bco) * C_ + ci0)
                             : ((size_t)bco * KDIM + ci0);
        uint32_t drow = (uint32_t)row * (RSTR * 2);
#pragma unroll
        for (int s = 0; s < 2; s++) {
            int qq = q0 + s;
            uint32_t doff = drow + qq * 16;
            cp16(base + 0 * ARRB + doff, A + asrc + qq * 8);
            cp16(base + 1 * ARRB + doff, BH + bsrc + qq * 8);
            if (TERMS == 2) cp16(base + 2 * ARRB + doff, BL + bsrc + qq * 8);
        }
        cp_commit();
    };

#pragma unroll
    for (int s = 0; s < STAGES - 1; s++) stage(s);
#pragma unroll 1
    for (int ch = 0; ch < NCH; ch++) {
        cp_wait<STAGES - 2>();
        __syncthreads();
        uint32_t base = smb + (uint32_t)(ch % STAGES) * CHUNKB;
        uint32_t aH = base, bH = base + ARRB, bL = base + 2 * ARRB;
#pragma unroll
        for (int k16 = 0; k16 < 2; k16++) {
            uint32_t koff = k16 * 32;
            uint32_t bhf[8], blf[8];
#pragma unroll
            for (int h = 0; h < 2; h++) {
                int n0 = wn * 32 + h * 16;
                ldm_x4(&bhf[h * 4], bH + (uint32_t)((n0 + b_row) * (RSTR * 2)) + b_kb + koff);
                if (TERMS == 2)
                    ldm_x4(&blf[h * 4], bL + (uint32_t)((n0 + b_row) * (RSTR * 2)) + b_kb + koff);
            }
#pragma unroll
            for (int mt = 0; mt < 4; mt++) {
                int m0 = wm * 64 + mt * 16;
                uint32_t af[4];
                ldm_x4(af, aH + (uint32_t)((m0 + a_row) * (RSTR * 2)) + a_kb + koff);
#pragma unroll
                for (int nt = 0; nt < 4; nt++) {
                    mma_f16(acc[mt][nt], af, &bhf[nt * 2]);
                    if (TERMS == 2) mma_f16(acc[mt][nt], af, &blf[nt * 2]);
                }
            }
        }
        if (ch + STAGES - 1 < NCH) stage(ch + STAGES - 1);
        else cp_commit();
    }

    // epilogue
    float sst[2][2] = {{0.f, 0.f}, {0.f, 0.f}};
    int bstart = (blockIdx.x * 128) / 225;
#pragma unroll
    for (int mt = 0; mt < 4; mt++) {
#pragma unroll
        for (int nt = 0; nt < 4; nt++) {
            int co2 = wn * 32 + nt * 8 + (lane & 3) * 2;
            int co = coBase + co2;
            float bv0 = __ldg(bias + co), bv1 = __ldg(bias + co + 1);
#pragma unroll
            for (int rr = 0; rr < 2; rr++) {
                int pr = blockIdx.x * 128 + wm * 64 + mt * 16 + (lane >> 2) + rr * 8;
                float v0 = acc[mt][nt][rr * 2 + 0] + bv0;
                float v1 = acc[mt][nt][rr * 2 + 1] + bv1;
                if (EPI != EPI_STEP) { v0 = elu_f(v0); v1 = elu_f(v1); }
                if (EPI == EPI_CONV) {
                    size_t o = (size_t)pr * 1024 + co_off + co;
                    *reinterpret_cast<__half2*>(oh + o) = __floats2half2_rn(v0, v1);
                } else if (EPI == EPI_FUSION) {
                    size_t o = (size_t)pr * 256 + co;
                    *reinterpret_cast<float2*>(of + o) = {v0, v1};
                    *reinterpret_cast<__half2*>(oh + o) = __floats2half2_rn(v0, v1);
                } else {
                    size_t o = (size_t)pr * 256 + co;
                    *reinterpret_cast<__half2*>(oh + o) = __floats2half2_rn(v0, v1);
                    int slot = pr / 225 - bstart;
                    sst[slot][0] += v0 + v1;
                    sst[slot][1] += v0 * v0 + v1 * v1;
                }
            }
        }
    }

    if (EPI == EPI_STEP) {
        __syncthreads();
        float* red = reinterpret_cast<float*>(sm);
        red[t * 4 + 0] = sst[0][0];
        red[t * 4 + 1] = sst[0][1];
        red[t * 4 + 2] = sst[1][0];
        red[t * 4 + 3] = sst[1][1];
        __syncthreads();
        for (int o2 = 128; o2 > 0; o2 >>= 1) {
            if (t < o2) {
#pragma unroll
                for (int k = 0; k < 4; k++) red[t * 4 + k] += red[(t + o2) * 4 + k];
            }
            __syncthreads();
        }
        if (t == 0) {
            int cta = blockIdx.y * MTILES + blockIdx.x;
#pragma unroll
            for (int k = 0; k < 4; k++) g_stats3[cta * 4 + k] = red[k];
        }
    }
}

// ---------------- per-step update (mu/rs derived inline; fp16 y + noise) -----
__global__ void __launch_bounds__(256)
step_update_kernel(const __half* __restrict__ ybuf,
                   float* __restrict__ xc,
                   __half* __restrict__ xch,
                   float* __restrict__ dout,
                   const float* __restrict__ sp_arr,
                   const float* __restrict__ ss_arr,
                   const float* __restrict__ rw_arr,
                   const float* __restrict__ prob_arr,
                   int step, int last)
{
    int b = blockIdx.x;
    int t = threadIdx.x;

    // combine y-stat partials for this batch (deterministic, identical per block)
    double s1d = 0.0, s2d = 0.0;
    int cxlo = (225 * b) >> 7;
    int cxhi = (225 * b + 224) >> 7;
    for (int cx = cxlo; cx <= cxhi; cx++) {
        int bstart = (cx * 128) / 225;
        int slot = b - bstart;
        if (slot >= 0 && slot < 2) {
            for (int cy = 0; cy < 2; cy++) {
                s1d += (double)g_stats3[(cy * MTILES + cx) * 4 + slot * 2 + 0];
                s2d += (double)g_stats3[(cy * MTILES + cx) * 4 + slot * 2 + 1];
            }
        }
    }
    const double n = (double)(C_ * HW_);
    double mu_d = s1d / n;
    double var_d = s2d / n - mu_d * mu_d;
    float mu = (float)mu_d;
    float rs = (float)(1.0 / sqrt(var_d + 1e-5));

    float sp = sp_arr[step];
    float cns = prob_arr[step] * ss_arr[step];
    float rw1 = 1.f + rw_arr[step];

    size_t bbase = (size_t)b * 57600;
    const __half* nz = g_nzh + (size_t)step * NELEM + bbase;

    float s1 = 0.f, s2 = 0.f;
#pragma unroll
    for (int e = 0; e < 15; e++) {
        int p = blockIdx.y * 15 + e;
        int j = p * 256 + t;
        float yv = __half2float(ybuf[bbase + j]);
        float d = (yv - mu) * rs;
        d = fmaf(d, g_lnwt[j], g_lnbt[j]);
        d = elu_f(d);
        s1 += d; s2 = fmaf(d, d, s2);
        float u = __half2float(nz[j]);
        float xn = fmaf(xc[bbase + j], rw1, fmaf(d, sp, u * cns));
        if (last) {
            dout[((size_t)b * 256 + t) * 225 + p] = xn;
        } else {
            xc[bbase + j] = xn;
            xch[bbase + j] = __float2half_rn(xn);
        }
    }

    __shared__ float red[256];
    red[t] = s1; __syncthreads();
    for (int off = 128; off > 0; off >>= 1) {
        if (t < off) red[t] += red[t + off];
        __syncthreads();
    }
    size_t sbase = ((size_t)step * B_ + b) * UPD_BLOCKS;
    if (t == 0) g_stats2[(sbase + blockIdx.y) * 2 + 0] = red[0];
    __syncthreads();
    red[t] = s2; __syncthreads();
    for (int off = 128; off > 0; off >>= 1) {
        if (t < off) red[t] += red[t + off];
        __syncthreads();
    }
    if (t == 0) g_stats2[(sbase + blockIdx.y) * 2 + 1] = red[0];
}

// ---------------- all-steps unbiased variance (single launch at end) --------
__global__ void var_final_kernel(float* __restrict__ out_var) {
    int step = blockIdx.x;
    int b = threadIdx.x;
    double s1 = 0.0, s2 = 0.0;
    size_t sbase = ((size_t)step * B_ + b) * UPD_BLOCKS;
    for (int k = 0; k < UPD_BLOCKS; k++) {
        s1 += (double)g_stats2[(sbase + k) * 2 + 0];
        s2 += (double)g_stats2[(sbase + k) * 2 + 1];
    }
    const double n = (double)(C_ * HW_);
    double v = (s2 - s1 * s1 / n) / (n - 1.0);
    out_var[b * S_ + step] = (float)v;
}

// ---------------- launch ----------------------------------------------------
extern "C" void kernel_launch(void* const* d_in, const int* in_sizes, int n_in,
                              void* d_out, int out_size) {
    const float* x    = (const float*)d_in[0];
    const float* prob = (const float*)d_in[1];
    const float* w3   = (const float*)d_in[2];
    const float* b3   = (const float*)d_in[3];
    const float* w3d  = (const float*)d_in[4];
    const float* b3d  = (const float*)d_in[5];
    const float* w5   = (const float*)d_in[6];
    const float* b5   = (const float*)d_in[7];
    const float* w7   = (const float*)d_in[8];
    const float* b7   = (const float*)d_in[9];
    const float* wf   = (const float*)d_in[10];
    const float* bf   = (const float*)d_in[11];
    const float* w1   = (const float*)d_in[12];
    const float* b1   = (const float*)d_in[13];
    const float* lnw  = (const float*)d_in[14];
    const float* lnb  = (const float*)d_in[15];
    const float* spar = (const float*)d_in[16];
    const float* ssc  = (const float*)d_in[17];
    const float* rwv  = (const float*)d_in[18];

    float* out = (float*)d_out;
    float* out_var = out + (size_t)NELEM;

    __half *xph, *wh, *wfh, *wfl, *w1h, *w1l, *cath, *xch, *ybufh;
    float *xc;
    cudaGetSymbolAddress((void**)&xph, g_xph);
    cudaGetSymbolAddress((void**)&wh, g_wh);
    cudaGetSymbolAddress((void**)&wfh, g_wfh);
    cudaGetSymbolAddress((void**)&wfl, g_wfl);
    cudaGetSymbolAddress((void**)&w1h, g_w1h);
    cudaGetSymbolAddress((void**)&w1l, g_w1l);
    cudaGetSymbolAddress((void**)&cath, g_cath);
    cudaGetSymbolAddress((void**)&xch, g_xch);
    cudaGetSymbolAddress((void**)&xc, g_xc);
    cudaGetSymbolAddress((void**)&ybufh, g_ybufh);

    static cudaStream_t s2 = nullptr;
    static cudaEvent_t evF;
    static cudaEvent_t evN[S_];
    if (!s2) {
        cudaStreamCreate(&s2);
        cudaEventCreateWithFlags(&evF, cudaEventDisableTiming);
        for (int i = 0; i < S_; i++) cudaEventCreateWithFlags(&evN[i], cudaEventDisableTiming);
    }

    cudaFuncSetAttribute(hmma_kernel<256, EPI_CONV, true, 1, 4>,
                         cudaFuncAttributeMaxDynamicSharedMemorySize, hsmem(1, 4));
    cudaFuncSetAttribute(hmma_kernel<1024, EPI_FUSION, false, 2, 3>,
                         cudaFuncAttributeMaxDynamicSharedMemorySize, hsmem(2, 3));
    cudaFuncSetAttribute(hmma_kernel<256, EPI_STEP, false, 2, 3>,
                         cudaFuncAttributeMaxDynamicSharedMemorySize, hsmem(2, 3));

    // fork: noise generation for all 8 steps on stream 2
    cudaEventRecord(evF, 0);
    cudaStreamWaitEvent(s2, evF, 0);
    for (int s = 0; s < S_; s++) {
        noise_kernel<<<dim3(B_, 15), 256, 0, s2>>>(s);
        cudaEventRecord(evN[s], s2);
    }

    // prep
    pad_h_kernel<<<dim3(B_, PADP * PADP), 256>>>(x);
    wconv_kernel<<<(C_ * C_ * 9 + 255) / 256, 256>>>(w3, 9, 0);
    wconv_kernel<<<(C_ * C_ * 9 + 255) / 256, 256>>>(w3d, 9, 9);
    wconv_kernel<<<(C_ * C_ * 25 + 255) / 256, 256>>>(w5, 25, 18);
    wconv_kernel<<<(C_ * C_ * 49 + 255) / 256, 256>>>(w7, 49, 43);
    wsplit1_kernel<<<(4 * C_ * C_ + 255) / 256, 256>>>(wf, wfh, wfl, 4 * C_ * C_);
    wsplit1_kernel<<<(C_ * C_ + 255) / 256, 256>>>(w1, w1h, w1l, C_ * C_);
    lnT_kernel<<<HW_, 256>>>(lnw, lnb);

    // all 4 multi-scale convs in ONE launch (z = conv id) -> cat (fp16)
    hmma_kernel<256, EPI_CONV, true, 1, 4><<<dim3(MTILES, 2, 4), 256, hsmem(1, 4)>>>(
        xph, wh, nullptr, b3, b3d, b5, b7, cath, nullptr);

    // fusion GEMM (K=1024) -> xc fp32 + xch fp16
    hmma_kernel<1024, EPI_FUSION, false, 2, 3><<<dim3(MTILES, 2), 256, hsmem(2, 3)>>>(
        cath, wfh, wfl, bf, bf, bf, bf, xch, xc);

    // 8 NCA steps: GEMM(+y-stat partials, fp16 y) -> update
    for (int i = 0; i < S_; i++) {
        hmma_kernel<256, EPI_STEP, false, 2, 3><<<dim3(MTILES, 2), 256, hsmem(2, 3)>>>(
            xch, w1h, w1l, b1, b1, b1, b1, ybufh, nullptr);
        cudaStreamWaitEvent(0, evN[i], 0);
        step_update_kernel<<<dim3(B_, UPD_BLOCKS), 256>>>(
            ybufh, xc, xch, out, spar, ssc, rwv, prob, i, i == S_ - 1);
    }
    var_final_kernel<<<S_, 256>>>(out_var);
}